// round 5
// baseline (speedup 1.0000x reference)
#include <cuda_runtime.h>
#include <cuda_bf16.h>

// Problem constants (fixed by the reference)
#define HS_N    4096
#define HS_P    10
#define HS_D    17
#define HS_PD   (HS_P * HS_D)   // 170 dot products per sample
#define HS_DIM  300             // embedding dim (75 float4)
#define HS_VEC4 (HS_DIM / 4)    // 75

__global__ __launch_bounds__(256, 8)
void skip_gram_hs_kernel(const int*   __restrict__ word_idx,   // [N]
                         const int*   __restrict__ paths,      // [N, P, D]
                         const int*   __restrict__ labels,     // [N, P, D]
                         const float* __restrict__ emb1,       // [VOCAB, DIM]
                         const float* __restrict__ emb2,       // [VOCAB-1, DIM]
                         float*       __restrict__ out,        // [N, P, D] sigmoid
                         float*       __restrict__ target)     // [N, P, D]
{
    __shared__ float4 s_proj[HS_VEC4];

    const int n   = blockIdx.x;
    const int tid = threadIdx.x;

    // Stage proj = emb1[word_idx[n]] into shared (75 float4 = 1200 B)
    const int w = word_idx[n];
    if (tid < HS_VEC4) {
        s_proj[tid] = reinterpret_cast<const float4*>(emb1 + (size_t)w * HS_DIM)[tid];
    }
    __syncthreads();

    const int warp = tid >> 5;
    const int lane = tid & 31;
    const int base = n * HS_PD;

    // 8 warps x ~21-22 dot products each
    for (int k = warp; k < HS_PD; k += 8) {
        const int idx = __ldg(paths + base + k);
        const float4* __restrict__ row =
            reinterpret_cast<const float4*>(emb2 + (size_t)idx * HS_DIM);

        // Lanes cover float4 indices lane, lane+32, lane+64 (< 75).
        // Issue loads before consuming -> MLP.
        float sum = 0.0f;
        {
            float4 a0 = __ldg(row + lane);
            float4 a1 = __ldg(row + lane + 32);
            float4 b0 = s_proj[lane];
            float4 b1 = s_proj[lane + 32];
            sum += a0.x * b0.x + a0.y * b0.y + a0.z * b0.z + a0.w * b0.w;
            sum += a1.x * b1.x + a1.y * b1.y + a1.z * b1.z + a1.w * b1.w;
            if (lane + 64 < HS_VEC4) {           // lanes 0..10
                float4 a2 = __ldg(row + lane + 64);
                float4 b2 = s_proj[lane + 64];
                sum += a2.x * b2.x + a2.y * b2.y + a2.z * b2.z + a2.w * b2.w;
            }
        }

        // Warp butterfly reduction
        #pragma unroll
        for (int off = 16; off > 0; off >>= 1)
            sum += __shfl_xor_sync(0xffffffffu, sum, off);

        if (lane == 0) {
            const float o = 1.0f / (1.0f + expf(-sum));
            // CRITICAL: threshold on the f32 sigmoid VALUE, not the logit sign.
            // sigmoid_f32(x) rounds to exactly 0.5 for a window of tiny-negative
            // x; the reference's (output >= 0.5) sees mask=1 there.
            const int mask = (o >= 0.5f) ? 1 : 0;
            const int lab  = labels[base + k];
            out[base + k]    = o;
            target[base + k] = (mask == lab) ? 1.0f : 0.0f;
        }
    }
}

extern "C" void kernel_launch(void* const* d_in, const int* in_sizes, int n_in,
                              void* d_out, int out_size)
{
    // metadata order: word_idx, paths, labels, emb1, emb2
    const int*   word_idx = (const int*)  d_in[0];
    const int*   paths    = (const int*)  d_in[1];
    const int*   labels   = (const int*)  d_in[2];
    const float* emb1     = (const float*)d_in[3];
    const float* emb2     = (const float*)d_in[4];

    float* out    = (float*)d_out;                        // first N*P*D: sigmoid
    float* target = (float*)d_out + (size_t)HS_N * HS_PD; // second N*P*D: target

    skip_gram_hs_kernel<<<HS_N, 256>>>(word_idx, paths, labels, emb1, emb2,
                                       out, target);
}

// round 6
// speedup vs baseline: 1.1564x; 1.1564x over previous
#include <cuda_runtime.h>
#include <cuda_bf16.h>

// Problem constants (fixed by the reference)
#define HS_N    4096
#define HS_P    10
#define HS_D    17
#define HS_PD   (HS_P * HS_D)   // 170 dot products per sample
#define HS_DIM  300             // embedding dim (75 float4)
#define HS_VEC4 (HS_DIM / 4)    // 75

__device__ __forceinline__ float dot4(float4 a, float4 b) {
    return a.x * b.x + a.y * b.y + a.z * b.z + a.w * b.w;
}

__global__ __launch_bounds__(256)
void skip_gram_hs_kernel(const int*   __restrict__ word_idx,   // [N]
                         const int*   __restrict__ paths,      // [N, P, D]
                         const int*   __restrict__ labels,     // [N, P, D]
                         const float* __restrict__ emb1,       // [VOCAB, DIM]
                         const float* __restrict__ emb2,       // [VOCAB-1, DIM]
                         float*       __restrict__ out,        // [N, P, D] sigmoid
                         float*       __restrict__ target)     // [N, P, D]
{
    const int n    = blockIdx.x;
    const int tid  = threadIdx.x;
    const int warp = tid >> 5;
    const int lane = tid & 31;
    const bool tail = (lane < HS_VEC4 - 64);   // lanes 0..10 own float4 #64..74

    // proj = emb1[word_idx[n]] held in REGISTERS per lane (no shared, no LDS
    // in the inner loop -- LDS was eating half the L1tex crossbar).
    const int w = __ldg(word_idx + n);
    const float4* __restrict__ prow =
        reinterpret_cast<const float4*>(emb1 + (size_t)w * HS_DIM);
    const float4 p0 = __ldg(prow + lane);
    const float4 p1 = __ldg(prow + lane + 32);
    const float4 p2 = tail ? __ldg(prow + lane + 64) : make_float4(0.f, 0.f, 0.f, 0.f);

    const int base = n * HS_PD;

    // 8 warps; each processes k = warp, warp+8, ... (~21 dot products),
    // two at a time for load MLP + interleaved shuffle chains.
    int k = warp;
    for (; k + 8 < HS_PD; k += 16) {
        const int idx0 = __ldg(paths + base + k);
        const int idx1 = __ldg(paths + base + k + 8);
        const float4* __restrict__ r0 =
            reinterpret_cast<const float4*>(emb2 + (size_t)idx0 * HS_DIM);
        const float4* __restrict__ r1 =
            reinterpret_cast<const float4*>(emb2 + (size_t)idx1 * HS_DIM);

        // Issue all 6 wide loads before consuming.
        float4 a0 = __ldg(r0 + lane);
        float4 a1 = __ldg(r0 + lane + 32);
        float4 b0 = __ldg(r1 + lane);
        float4 b1 = __ldg(r1 + lane + 32);
        float4 a2 = make_float4(0.f, 0.f, 0.f, 0.f);
        float4 b2 = make_float4(0.f, 0.f, 0.f, 0.f);
        if (tail) { a2 = __ldg(r0 + lane + 64); b2 = __ldg(r1 + lane + 64); }

        float s0 = dot4(a0, p0) + dot4(a1, p1) + dot4(a2, p2);
        float s1 = dot4(b0, p0) + dot4(b1, p1) + dot4(b2, p2);

        // Two independent butterfly chains, interleaved.
        #pragma unroll
        for (int off = 16; off > 0; off >>= 1) {
            s0 += __shfl_xor_sync(0xffffffffu, s0, off);
            s1 += __shfl_xor_sync(0xffffffffu, s1, off);
        }

        if (lane == 0) {
            const float o0 = 1.0f / (1.0f + expf(-s0));
            const float o1 = 1.0f / (1.0f + expf(-s1));
            // Threshold the f32 sigmoid VALUE (matches reference rounding at 0.5).
            const int m0 = (o0 >= 0.5f) ? 1 : 0;
            const int m1 = (o1 >= 0.5f) ? 1 : 0;
            const int l0 = labels[base + k];
            const int l1 = labels[base + k + 8];
            out[base + k]        = o0;
            out[base + k + 8]    = o1;
            target[base + k]     = (m0 == l0) ? 1.0f : 0.0f;
            target[base + k + 8] = (m1 == l1) ? 1.0f : 0.0f;
        }
    }

    // Remainder (at most one k per warp)
    if (k < HS_PD) {
        const int idx = __ldg(paths + base + k);
        const float4* __restrict__ row =
            reinterpret_cast<const float4*>(emb2 + (size_t)idx * HS_DIM);

        float4 a0 = __ldg(row + lane);
        float4 a1 = __ldg(row + lane + 32);
        float4 a2 = make_float4(0.f, 0.f, 0.f, 0.f);
        if (tail) a2 = __ldg(row + lane + 64);

        float s = dot4(a0, p0) + dot4(a1, p1) + dot4(a2, p2);

        #pragma unroll
        for (int off = 16; off > 0; off >>= 1)
            s += __shfl_xor_sync(0xffffffffu, s, off);

        if (lane == 0) {
            const float o = 1.0f / (1.0f + expf(-s));
            const int m = (o >= 0.5f) ? 1 : 0;
            const int l = labels[base + k];
            out[base + k]    = o;
            target[base + k] = (m == l) ? 1.0f : 0.0f;
        }
    }
}

extern "C" void kernel_launch(void* const* d_in, const int* in_sizes, int n_in,
                              void* d_out, int out_size)
{
    // metadata order: word_idx, paths, labels, emb1, emb2
    const int*   word_idx = (const int*)  d_in[0];
    const int*   paths    = (const int*)  d_in[1];
    const int*   labels   = (const int*)  d_in[2];
    const float* emb1     = (const float*)d_in[3];
    const float* emb2     = (const float*)d_in[4];

    float* out    = (float*)d_out;                        // first N*P*D: sigmoid
    float* target = (float*)d_out + (size_t)HS_N * HS_PD; // second N*P*D: target

    skip_gram_hs_kernel<<<HS_N, 256>>>(word_idx, paths, labels, emb1, emb2,
                                       out, target);
}